// round 2
// baseline (speedup 1.0000x reference)
#include <cuda_runtime.h>
#include <cuda_bf16.h>
#include <mma.h>
#include <math.h>

using namespace nvcuda;

// Problem shape constants
#define BATCHN   4
#define SEQ      1024
#define DMODEL   4096
#define NHEAD    32
#define HDIM     128
#define TOKENS   (BATCHN * SEQ)      // 4096
#define ROTARY_N 32
#define MAX_POS  10000

// ---------------------------------------------------------------------------
// Scratch (device globals; cudaMalloc is banned).
// NOTE: attention output O aliases g_q — Q is dead once the scores GEMM is
// done, and the PV GEMM reads only g_sc and g_v.
// ---------------------------------------------------------------------------
__device__ float g_q[(size_t)TOKENS * DMODEL];                      // 64 MB (later: O)
__device__ float g_k[(size_t)TOKENS * DMODEL];                      // 64 MB
__device__ float g_v[(size_t)TOKENS * DMODEL];                      // 64 MB
__device__ float g_sc[(size_t)BATCHN * NHEAD * SEQ * SEQ];          // 512 MB
__device__ float g_cos[SEQ * (ROTARY_N / 2)];
__device__ float g_sin[SEQ * (ROTARY_N / 2)];

// ---------------------------------------------------------------------------
// Rotary table: computed in double to match numpy float64 -> fp32 rounding
// ---------------------------------------------------------------------------
__global__ void rotary_table_kernel() {
    int idx = blockIdx.x * blockDim.x + threadIdx.x;
    if (idx >= SEQ * (ROTARY_N / 2)) return;
    int s = idx >> 4;          // 16 freqs per position
    int i = idx & 15;
    double inv = pow(10000.0, -((double)(2 * i)) / (double)ROTARY_N);
    double ang = (double)(MAX_POS - SEQ + s) * inv;
    g_cos[idx] = (float)cos(ang);
    g_sin[idx] = (float)sin(ang);
}

// ---------------------------------------------------------------------------
// Rotary apply (in-place on q and k, first 32 channels of each head).
// One thread owns a full (token, head) 32-channel group (avoids the
// read/write permutation race). 131072 threads.
// ---------------------------------------------------------------------------
__global__ void rotary_apply_kernel(float* __restrict__ q, float* __restrict__ k) {
    int idx = blockIdx.x * blockDim.x + threadIdx.x;
    if (idx >= TOKENS * NHEAD) return;
    int token = idx >> 5;
    int h     = idx & 31;
    int s     = token & (SEQ - 1);
    long long base = (long long)token * DMODEL + h * HDIM;
    const float* cs = g_cos + s * 16;
    const float* sn = g_sin + s * 16;

    float* ptrs[2] = {q, k};
#pragma unroll
    for (int w = 0; w < 2; w++) {
        float* p = ptrs[w] + base;
        float buf[32], out[32];
#pragma unroll
        for (int i = 0; i < 8; i++) ((float4*)buf)[i] = ((const float4*)p)[i];
#pragma unroll
        for (int i = 0; i < 16; i++) {
            float re = buf[i], im = buf[16 + i];
            float c = cs[i], sv = sn[i];
            out[2 * i]     = re * c - im * sv;
            out[2 * i + 1] = re * sv + im * c;
        }
#pragma unroll
        for (int i = 0; i < 8; i++) ((float4*)p)[i] = ((float4*)out)[i];
    }
}

// ---------------------------------------------------------------------------
// Generic batched TF32 wmma GEMM.
//   C[m][n] = scale * sum_k A[m][k] * B(k, n)  (+ biasN[n]) (+ bias2d[m][n])
// B_COL = true means B is accessed as B[n*ldb + k] (i.e., K^T from a row-major
// K tensor). All of M, N must be multiples of 128; K multiple of 32.
// Batch offset: z -> (z / nInner, z % nInner) with per-matrix stride pairs.
// CTA: 128x128 tile, 256 threads (8 warps as 2x4, warp tile 64x32),
// BK=32, double-buffered smem, epilogue staged through smem.
// ---------------------------------------------------------------------------
constexpr int BM = 128, BN = 128, BK = 32;
constexpr int ASTRIDE = 36;    // padded smem stride (floats), 144B (16B mult)
constexpr int BSTRIDE_ROW = 132;
constexpr int BUF_FLOATS = 4608;                  // 128*36
constexpr int SMEM_FLOATS = 4 * BUF_FLOATS;       // A0,B0,A1,B1
constexpr int SMEM_BYTES = SMEM_FLOATS * 4;       // 73728
constexpr int CB_STRIDE = 132;                    // epilogue staging stride

template <bool B_COL, bool HAS_BIASN, bool HAS_BIAS2D>
__global__ __launch_bounds__(256) void gemm_tf32_kernel(
    const float* __restrict__ A, int lda, long long outerA, long long innerA,
    const float* __restrict__ B, int ldb, long long outerB, long long innerB,
    float* __restrict__ C,       int ldc, long long outerC, long long innerC,
    int K, int nInner,
    const float* __restrict__ biasN,
    const float* __restrict__ bias2d, int ldBias2d,
    float scale)
{
    extern __shared__ float sm[];
    float* Abuf0 = sm;
    float* Bbuf0 = sm + BUF_FLOATS;
    float* Abuf1 = sm + 2 * BUF_FLOATS;
    float* Bbuf1 = sm + 3 * BUF_FLOATS;

    const int tid  = threadIdx.x;
    const int warp = tid >> 5;
    const int wm   = warp >> 2;   // 0..1
    const int wn   = warp & 3;    // 0..3
    const int m0   = blockIdx.y * BM;
    const int n0   = blockIdx.x * BN;

    {
        int z  = blockIdx.z;
        int zo = z / nInner;
        int zi = z - zo * nInner;
        A += (long long)zo * outerA + (long long)zi * innerA;
        B += (long long)zo * outerB + (long long)zi * innerB;
        C += (long long)zo * outerC + (long long)zi * innerC;
    }

    wmma::fragment<wmma::accumulator, 16, 16, 8, float> acc[4][2];
#pragma unroll
    for (int i = 0; i < 4; i++)
#pragma unroll
        for (int j = 0; j < 2; j++) wmma::fill_fragment(acc[i][j], 0.0f);

    const int nK = K / BK;

    auto load_tiles = [&](int kt, float* aDst, float* bDst) {
        const float* aSrc = A + (long long)m0 * lda + kt * BK;
#pragma unroll
        for (int i = 0; i < 4; i++) {
            int f = tid + i * 256;
            int r = f >> 3;
            int c = (f & 7) << 2;
            *(float4*)(aDst + r * ASTRIDE + c) =
                *(const float4*)(aSrc + (long long)r * lda + c);
        }
        if constexpr (B_COL) {
            const float* bSrc = B + (long long)n0 * ldb + kt * BK;
#pragma unroll
            for (int i = 0; i < 4; i++) {
                int f = tid + i * 256;
                int r = f >> 3;
                int c = (f & 7) << 2;
                *(float4*)(bDst + r * ASTRIDE + c) =
                    *(const float4*)(bSrc + (long long)r * ldb + c);
            }
        } else {
            const float* bSrc = B + (long long)kt * BK * ldb + n0;
#pragma unroll
            for (int i = 0; i < 4; i++) {
                int f = tid + i * 256;
                int r = f >> 5;
                int c = (f & 31) << 2;
                *(float4*)(bDst + r * BSTRIDE_ROW + c) =
                    *(const float4*)(bSrc + (long long)r * ldb + c);
            }
        }
    };

    load_tiles(0, Abuf0, Bbuf0);
    __syncthreads();

    for (int kt = 0; kt < nK; kt++) {
        const int cur = kt & 1;
        float* asw = cur ? Abuf1 : Abuf0;
        float* bsw = cur ? Bbuf1 : Bbuf0;
        if (kt + 1 < nK) load_tiles(kt + 1, cur ? Abuf0 : Abuf1, cur ? Bbuf0 : Bbuf1);
        const float* as = asw;
        const float* bs = bsw;

#pragma unroll
        for (int ks = 0; ks < 4; ks++) {
            wmma::fragment<wmma::matrix_a, 16, 16, 8, wmma::precision::tf32,
                           wmma::row_major> af[4];
#pragma unroll
            for (int i = 0; i < 4; i++) {
                wmma::load_matrix_sync(af[i], as + (wm * 64 + i * 16) * ASTRIDE + ks * 8,
                                       ASTRIDE);
#pragma unroll
                for (int e = 0; e < af[i].num_elements; e++)
                    af[i].x[e] = wmma::__float_to_tf32(af[i].x[e]);
            }
            if constexpr (B_COL) {
                wmma::fragment<wmma::matrix_b, 16, 16, 8, wmma::precision::tf32,
                               wmma::col_major> bf[2];
#pragma unroll
                for (int j = 0; j < 2; j++) {
                    wmma::load_matrix_sync(bf[j],
                                           bs + (wn * 32 + j * 16) * ASTRIDE + ks * 8,
                                           ASTRIDE);
#pragma unroll
                    for (int e = 0; e < bf[j].num_elements; e++)
                        bf[j].x[e] = wmma::__float_to_tf32(bf[j].x[e]);
                }
#pragma unroll
                for (int i = 0; i < 4; i++)
#pragma unroll
                    for (int j = 0; j < 2; j++)
                        wmma::mma_sync(acc[i][j], af[i], bf[j], acc[i][j]);
            } else {
                wmma::fragment<wmma::matrix_b, 16, 16, 8, wmma::precision::tf32,
                               wmma::row_major> bf[2];
#pragma unroll
                for (int j = 0; j < 2; j++) {
                    wmma::load_matrix_sync(bf[j],
                                           bs + ks * 8 * BSTRIDE_ROW + wn * 32 + j * 16,
                                           BSTRIDE_ROW);
#pragma unroll
                    for (int e = 0; e < bf[j].num_elements; e++)
                        bf[j].x[e] = wmma::__float_to_tf32(bf[j].x[e]);
                }
#pragma unroll
                for (int i = 0; i < 4; i++)
#pragma unroll
                    for (int j = 0; j < 2; j++)
                        wmma::mma_sync(acc[i][j], af[i], bf[j], acc[i][j]);
            }
        }
        __syncthreads();
    }

    // Epilogue: stage through smem, then fused scale/bias + coalesced store.
    float* cb = sm;
#pragma unroll
    for (int i = 0; i < 4; i++)
#pragma unroll
        for (int j = 0; j < 2; j++)
            wmma::store_matrix_sync(cb + (wm * 64 + i * 16) * CB_STRIDE + wn * 32 + j * 16,
                                    acc[i][j], CB_STRIDE, wmma::mem_row_major);
    __syncthreads();

    const float* b2 = HAS_BIAS2D ? (bias2d + (long long)m0 * ldBias2d + n0) : nullptr;
#pragma unroll
    for (int i = 0; i < 16; i++) {
        int f = tid + i * 256;
        int r = f >> 5;
        int c = (f & 31) << 2;
        float4 v = *(float4*)(cb + r * CB_STRIDE + c);
        v.x *= scale; v.y *= scale; v.z *= scale; v.w *= scale;
        if constexpr (HAS_BIASN) {
            float4 bn = *(const float4*)(biasN + n0 + c);
            v.x += bn.x; v.y += bn.y; v.z += bn.z; v.w += bn.w;
        }
        if constexpr (HAS_BIAS2D) {
            float4 bb = *(const float4*)(b2 + (long long)r * ldBias2d + c);
            v.x += bb.x; v.y += bb.y; v.z += bb.z; v.w += bb.w;
        }
        *(float4*)(C + (long long)(m0 + r) * ldc + n0 + c) = v;
    }
}

// ---------------------------------------------------------------------------
// Row softmax over 1024 elements; one 128-thread block per row.
// ---------------------------------------------------------------------------
__global__ void softmax_kernel(float* __restrict__ S) {
    __shared__ float red[8];
    const long long row = blockIdx.x;
    float* p = S + row * SEQ;
    const int t = threadIdx.x;

    float4 a = ((const float4*)p)[t];
    float4 b = ((const float4*)p)[t + 128];
    float m = fmaxf(fmaxf(fmaxf(a.x, a.y), fmaxf(a.z, a.w)),
                    fmaxf(fmaxf(b.x, b.y), fmaxf(b.z, b.w)));
#pragma unroll
    for (int o = 16; o > 0; o >>= 1) m = fmaxf(m, __shfl_xor_sync(0xffffffffu, m, o));
    if ((t & 31) == 0) red[t >> 5] = m;
    __syncthreads();
    m = fmaxf(fmaxf(red[0], red[1]), fmaxf(red[2], red[3]));

    a.x = expf(a.x - m); a.y = expf(a.y - m); a.z = expf(a.z - m); a.w = expf(a.w - m);
    b.x = expf(b.x - m); b.y = expf(b.y - m); b.z = expf(b.z - m); b.w = expf(b.w - m);
    float s = a.x + a.y + a.z + a.w + b.x + b.y + b.z + b.w;
#pragma unroll
    for (int o = 16; o > 0; o >>= 1) s += __shfl_xor_sync(0xffffffffu, s, o);
    if ((t & 31) == 0) red[4 + (t >> 5)] = s;
    __syncthreads();
    s = red[4] + red[5] + red[6] + red[7];
    float inv = 1.0f / s;

    a.x *= inv; a.y *= inv; a.z *= inv; a.w *= inv;
    b.x *= inv; b.y *= inv; b.z *= inv; b.w *= inv;
    ((float4*)p)[t]       = a;
    ((float4*)p)[t + 128] = b;
}

// ---------------------------------------------------------------------------
// Host launcher
// ---------------------------------------------------------------------------
extern "C" void kernel_launch(void* const* d_in, const int* in_sizes, int n_in,
                              void* d_out, int out_size) {
    (void)in_sizes; (void)n_in; (void)out_size;
    const float* x    = (const float*)d_in[0];
    const float* abia = (const float*)d_in[1];
    const float* wq   = (const float*)d_in[2];
    const float* bq   = (const float*)d_in[3];
    const float* wk   = (const float*)d_in[4];
    const float* bk   = (const float*)d_in[5];
    const float* wv   = (const float*)d_in[6];
    const float* bv   = (const float*)d_in[7];
    const float* wo   = (const float*)d_in[8];
    const float* bo   = (const float*)d_in[9];
    float* out = (float*)d_out;

    void* p;
    cudaGetSymbolAddress(&p, g_q);  float* q  = (float*)p;
    cudaGetSymbolAddress(&p, g_k);  float* k  = (float*)p;
    cudaGetSymbolAddress(&p, g_v);  float* v  = (float*)p;
    cudaGetSymbolAddress(&p, g_sc); float* sc = (float*)p;
    float* o = q;   // alias: Q is dead after the scores GEMM

    cudaFuncSetAttribute(gemm_tf32_kernel<false, true,  false>,
                         cudaFuncAttributeMaxDynamicSharedMemorySize, SMEM_BYTES);
    cudaFuncSetAttribute(gemm_tf32_kernel<true,  false, true>,
                         cudaFuncAttributeMaxDynamicSharedMemorySize, SMEM_BYTES);
    cudaFuncSetAttribute(gemm_tf32_kernel<false, false, false>,
                         cudaFuncAttributeMaxDynamicSharedMemorySize, SMEM_BYTES);

    // 1) Rotary tables
    rotary_table_kernel<<<(SEQ * 16 + 255) / 256, 256>>>();

    // 2) QKV projections: [4096,4096] x [4096,4096] + bias
    {
        dim3 grid(DMODEL / BN, TOKENS / BM, 1);
        gemm_tf32_kernel<false, true, false><<<grid, 256, SMEM_BYTES>>>(
            x, DMODEL, 0, 0, wq, DMODEL, 0, 0, q, DMODEL, 0, 0,
            DMODEL, 1, bq, nullptr, 0, 1.0f);
        gemm_tf32_kernel<false, true, false><<<grid, 256, SMEM_BYTES>>>(
            x, DMODEL, 0, 0, wk, DMODEL, 0, 0, k, DMODEL, 0, 0,
            DMODEL, 1, bk, nullptr, 0, 1.0f);
        gemm_tf32_kernel<false, true, false><<<grid, 256, SMEM_BYTES>>>(
            x, DMODEL, 0, 0, wv, DMODEL, 0, 0, v, DMODEL, 0, 0,
            DMODEL, 1, bv, nullptr, 0, 1.0f);
    }

    // 3) Rotary on q, k
    rotary_apply_kernel<<<(TOKENS * NHEAD + 255) / 256, 256>>>(q, k);

    // 4) Scores: S[bh] = Q_bh * K_bh^T / sqrt(HD) + attn_bias
    {
        dim3 grid(SEQ / BN, SEQ / BM, BATCHN * NHEAD);
        const long long tokD = (long long)SEQ * DMODEL;      // per-batch A/B stride
        const long long scO  = (long long)NHEAD * SEQ * SEQ; // per-batch C stride
        gemm_tf32_kernel<true, false, true><<<grid, 256, SMEM_BYTES>>>(
            q, DMODEL, tokD, HDIM,
            k, DMODEL, tokD, HDIM,
            sc, SEQ, scO, (long long)SEQ * SEQ,
            HDIM, NHEAD,
            nullptr, abia, SEQ, 0.08838834764831845f);
    }

    // 5) Softmax over rows
    softmax_kernel<<<BATCHN * NHEAD * SEQ, 128>>>(sc);

    // 6) O = P * V   (O aliases g_q; Q no longer needed)
    {
        dim3 grid(HDIM / BN, SEQ / BM, BATCHN * NHEAD);
        const long long tokD = (long long)SEQ * DMODEL;
        const long long scO  = (long long)NHEAD * SEQ * SEQ;
        gemm_tf32_kernel<false, false, false><<<grid, 256, SMEM_BYTES>>>(
            sc, SEQ, scO, (long long)SEQ * SEQ,
            v, DMODEL, tokD, HDIM,
            o, DMODEL, tokD, HDIM,
            SEQ, NHEAD,
            nullptr, nullptr, 0, 1.0f);
    }

    // 7) Output projection: out = O * Wo + bo
    {
        dim3 grid(DMODEL / BN, TOKENS / BM, 1);
        gemm_tf32_kernel<false, true, false><<<grid, 256, SMEM_BYTES>>>(
            o, DMODEL, 0, 0, wo, DMODEL, 0, 0, out, DMODEL, 0, 0,
            DMODEL, 1, bo, nullptr, 0, 1.0f);
    }
}